// round 1
// baseline (speedup 1.0000x reference)
#include <cuda_runtime.h>
#include <math.h>

#define S_DIM 256
#define B_DIM 512
#define H_DIM 512
#define E_DIM 256
#define L_DIM 4
#define OUT_DIM 128
#define G3H (3 * H_DIM)

// ---------------- scratch (no allocations allowed) ----------------
__device__ float g_ubwh[B_DIM * H_DIM];          // Ub[o] + Wb[o] + h_last @ Ww^T
__device__ float g_energy[S_DIM * B_DIM];
__device__ float g_att[S_DIM * B_DIM];
__device__ float g_rnnin[B_DIM * (H_DIM + E_DIM)];
__device__ float g_gi[B_DIM * G3H];
__device__ float g_gh[B_DIM * G3H];

__device__ __forceinline__ float sigm(float x) { return 1.0f / (1.0f + expf(-x)); }

// =====================================================================
// Generic GEMM:  C[m,n] = sum_k A[m,k] * W[n,k] + bias[n] (+ bias2[n])
// A row-major [M,K], W row-major [N,K], C row-major [M,N]
// BM=64, BN=128, TK=16, 256 threads, 4x8 microtile.
// Requires M%64==0, N%128==0, K%16==0 (true for all shapes here).
// =====================================================================
__global__ __launch_bounds__(256) void gemm_tn(
    const float* __restrict__ A, const float* __restrict__ W,
    const float* __restrict__ bias, const float* __restrict__ bias2,
    float* __restrict__ C, int M, int N, int K)
{
    __shared__ float As[16][68];    // [k][m]
    __shared__ float Ws[16][132];   // [k][n]

    const int tid = threadIdx.x;
    const int tx = tid & 15;        // 0..15 -> n micro (8 wide)
    const int ty = tid >> 4;        // 0..15 -> m micro (4 tall)
    const int m0 = blockIdx.y * 64;
    const int n0 = blockIdx.x * 128;

    const int ar  = tid >> 2;           // 0..63
    const int akq = (tid & 3) * 4;      // 0,4,8,12
    const int wr0 = tid >> 2;           // 0..63
    const int wr1 = (tid + 256) >> 2;   // 64..127
    const int wk0 = (tid & 3) * 4;

    float acc[4][8];
#pragma unroll
    for (int i = 0; i < 4; i++)
#pragma unroll
        for (int j = 0; j < 8; j++) acc[i][j] = 0.0f;

    for (int k0 = 0; k0 < K; k0 += 16) {
        float4 av  = *(const float4*)(A + (size_t)(m0 + ar) * K + k0 + akq);
        float4 wv0 = *(const float4*)(W + (size_t)(n0 + wr0) * K + k0 + wk0);
        float4 wv1 = *(const float4*)(W + (size_t)(n0 + wr1) * K + k0 + wk0);
        __syncthreads();
        As[akq + 0][ar] = av.x; As[akq + 1][ar] = av.y;
        As[akq + 2][ar] = av.z; As[akq + 3][ar] = av.w;
        Ws[wk0 + 0][wr0] = wv0.x; Ws[wk0 + 1][wr0] = wv0.y;
        Ws[wk0 + 2][wr0] = wv0.z; Ws[wk0 + 3][wr0] = wv0.w;
        Ws[wk0 + 0][wr1] = wv1.x; Ws[wk0 + 1][wr1] = wv1.y;
        Ws[wk0 + 2][wr1] = wv1.z; Ws[wk0 + 3][wr1] = wv1.w;
        __syncthreads();
#pragma unroll
        for (int kk = 0; kk < 16; kk++) {
            float a[4], w[8];
            *(float4*)&a[0] = *(const float4*)&As[kk][ty * 4];
            *(float4*)&w[0] = *(const float4*)&Ws[kk][tx * 8];
            *(float4*)&w[4] = *(const float4*)&Ws[kk][tx * 8 + 4];
#pragma unroll
            for (int i = 0; i < 4; i++)
#pragma unroll
                for (int j = 0; j < 8; j++) acc[i][j] += a[i] * w[j];
        }
    }

    float bb[8];
#pragma unroll
    for (int j = 0; j < 8; j++) {
        int n = n0 + tx * 8 + j;
        bb[j] = bias[n] + (bias2 ? bias2[n] : 0.0f);
    }
#pragma unroll
    for (int i = 0; i < 4; i++) {
        int m = m0 + ty * 4 + i;
#pragma unroll
        for (int j = 0; j < 8; j++)
            C[(size_t)m * N + n0 + tx * 8 + j] = acc[i][j] + bb[j];
    }
}

// =====================================================================
// Fused energy kernel:
// energy[s,b] = sum_o tanh( (ES[s,b,:] . Uw[o,:]) + ubwh[b,o] ) * aw[o]
// Block: 128 rows (s,b pairs, contiguous => single s, contiguous b),
// loops o in 4 tiles of 128, K-step 8, 8x8 microtile per thread.
// =====================================================================
__global__ __launch_bounds__(256) void energy_kernel(
    const float* __restrict__ ES, const float* __restrict__ Uw,
    const float* __restrict__ aw)
{
    __shared__ float As[8][132];
    __shared__ float Ws[8][132];
    __shared__ float awS[512];
    __shared__ float red[128][17];

    const int tid = threadIdx.x;
    const int tx = tid & 15;
    const int ty = tid >> 4;
    const int rowBase = blockIdx.x * 128;       // global row = s*B + b
    const int b0 = rowBase & (B_DIM - 1);       // block spans one s, contiguous b

    for (int i = tid; i < 512; i += 256) awS[i] = aw[i];

    const int r_ld  = tid >> 1;       // 0..127
    const int kq_ld = (tid & 1) * 4;  // 0 or 4

    float rowpart[8];
#pragma unroll
    for (int i = 0; i < 8; i++) rowpart[i] = 0.0f;

    for (int ot = 0; ot < 4; ++ot) {
        float C[8][8];
#pragma unroll
        for (int i = 0; i < 8; i++)
#pragma unroll
            for (int j = 0; j < 8; j++) C[i][j] = 0.0f;

        for (int k0 = 0; k0 < 512; k0 += 8) {
            float4 av = *(const float4*)(ES + (size_t)(rowBase + r_ld) * 512 + k0 + kq_ld);
            float4 wv = *(const float4*)(Uw + (size_t)(ot * 128 + r_ld) * 512 + k0 + kq_ld);
            __syncthreads();
            As[kq_ld + 0][r_ld] = av.x; As[kq_ld + 1][r_ld] = av.y;
            As[kq_ld + 2][r_ld] = av.z; As[kq_ld + 3][r_ld] = av.w;
            Ws[kq_ld + 0][r_ld] = wv.x; Ws[kq_ld + 1][r_ld] = wv.y;
            Ws[kq_ld + 2][r_ld] = wv.z; Ws[kq_ld + 3][r_ld] = wv.w;
            __syncthreads();
#pragma unroll
            for (int kk = 0; kk < 8; kk++) {
                float a[8], w[8];
                *(float4*)&a[0] = *(const float4*)&As[kk][ty * 8];
                *(float4*)&a[4] = *(const float4*)&As[kk][ty * 8 + 4];
                *(float4*)&w[0] = *(const float4*)&Ws[kk][tx * 8];
                *(float4*)&w[4] = *(const float4*)&Ws[kk][tx * 8 + 4];
#pragma unroll
                for (int i = 0; i < 8; i++)
#pragma unroll
                    for (int j = 0; j < 8; j++) C[i][j] += a[i] * w[j];
            }
        }

        // epilogue: tanh(C + ubwh) * aw, reduce over this o-tile's 8 cols
        float awv[8];
#pragma unroll
        for (int j = 0; j < 8; j++) awv[j] = awS[ot * 128 + tx * 8 + j];
#pragma unroll
        for (int i = 0; i < 8; i++) {
            int b = b0 + ty * 8 + i;
            const float* up = g_ubwh + (size_t)b * 512 + ot * 128 + tx * 8;
            float u[8];
            *(float4*)&u[0] = *(const float4*)(up);
            *(float4*)&u[4] = *(const float4*)(up + 4);
            float p = 0.0f;
#pragma unroll
            for (int j = 0; j < 8; j++)
                p += tanhf(C[i][j] + u[j]) * awv[j];
            rowpart[i] += p;
        }
    }

    __syncthreads();
#pragma unroll
    for (int i = 0; i < 8; i++) red[ty * 8 + i][tx] = rowpart[i];
    __syncthreads();
    if (tid < 128) {
        float e = 0.0f;
#pragma unroll
        for (int t = 0; t < 16; t++) e += red[tid][t];
        g_energy[rowBase + tid] = e;
    }
}

// softmax over S per column b (one thread per b, fixed-order => deterministic)
__global__ void softmax_kernel()
{
    int b = blockIdx.x * blockDim.x + threadIdx.x;
    if (b >= B_DIM) return;
    float m = -1e30f;
    for (int s = 0; s < S_DIM; s++) m = fmaxf(m, g_energy[s * B_DIM + b]);
    float sum = 0.0f;
    for (int s = 0; s < S_DIM; s++) {
        float e = expf(g_energy[s * B_DIM + b] - m);
        g_att[s * B_DIM + b] = e;
        sum += e;
    }
    float inv = 1.0f / sum;
    for (int s = 0; s < S_DIM; s++) g_att[s * B_DIM + b] *= inv;
}

// context[b,h] = sum_s att[s,b] * ES[s,b,h]  ->  rnn_in[b, 0:H]
__global__ void context_kernel(const float* __restrict__ ES)
{
    const int b  = blockIdx.x;
    const int tx = threadIdx.x;   // 0..127 (h/4)
    const int sy = threadIdx.y;   // 0..1   (s half)
    __shared__ float attS[256];
    __shared__ float4 buf[128];

    int tid = sy * 128 + tx;
    attS[tid] = g_att[tid * B_DIM + b];
    __syncthreads();

    float4 acc = make_float4(0.f, 0.f, 0.f, 0.f);
    const float4* base = (const float4*)ES;
    int s0 = sy * 128;
#pragma unroll 4
    for (int s = s0; s < s0 + 128; ++s) {
        float a = attS[s];
        float4 v = base[(size_t)(s * B_DIM + b) * 128 + tx];
        acc.x += a * v.x; acc.y += a * v.y; acc.z += a * v.z; acc.w += a * v.w;
    }
    if (sy == 1) buf[tx] = acc;
    __syncthreads();
    if (sy == 0) {
        float4 o = buf[tx];
        acc.x += o.x; acc.y += o.y; acc.z += o.z; acc.w += o.w;
        *(float4*)(g_rnnin + (size_t)b * (H_DIM + E_DIM) + tx * 4) = acc;
    }
}

// rnn_in[b, H : H+E] = emb[x[b]]
__global__ void embed_kernel(const int* __restrict__ x, const float* __restrict__ emb)
{
    int idx = blockIdx.x * blockDim.x + threadIdx.x;  // < B*E
    if (idx >= B_DIM * E_DIM) return;
    int b = idx >> 8, e = idx & 255;
    g_rnnin[(size_t)b * (H_DIM + E_DIM) + H_DIM + e] = emb[(size_t)x[b] * E_DIM + e];
}

// GRU gate math
__global__ void gru_gate(const float* __restrict__ hprev, float* __restrict__ hout)
{
    int idx = blockIdx.x * blockDim.x + threadIdx.x;  // < B*H
    if (idx >= B_DIM * H_DIM) return;
    int b = idx >> 9, j = idx & 511;
    const float* gib = g_gi + (size_t)b * G3H;
    const float* ghb = g_gh + (size_t)b * G3H;
    float r = sigm(gib[j] + ghb[j]);
    float z = sigm(gib[H_DIM + j] + ghb[H_DIM + j]);
    float n = tanhf(gib[2 * H_DIM + j] + r * ghb[2 * H_DIM + j]);
    hout[idx] = (1.0f - z) * n + z * hprev[idx];
}

// =====================================================================
extern "C" void kernel_launch(void* const* d_in, const int* in_sizes, int n_in,
                              void* d_out, int out_size)
{
    const int*   x      = (const int*)  d_in[0];
    const float* ES     = (const float*)d_in[1];
    const float* hidden = (const float*)d_in[2];
    // d_in[3] = cell (unused)
    const float* emb    = (const float*)d_in[4];
    const float* Uw     = (const float*)d_in[5];
    const float* Ub     = (const float*)d_in[6];
    const float* Ww     = (const float*)d_in[7];
    const float* Wb     = (const float*)d_in[8];
    const float* aw     = (const float*)d_in[9];
    // d_in[10] = ab (irrelevant: softmax shift-invariant)
    const float* w_ih0  = (const float*)d_in[11];
    const float* w_hh0  = (const float*)d_in[12];
    const float* b_ih0  = (const float*)d_in[13];
    const float* b_hh0  = (const float*)d_in[14];
    const float* w_ih_r = (const float*)d_in[15];
    const float* w_hh_r = (const float*)d_in[16];
    const float* b_ih_r = (const float*)d_in[17];
    const float* b_hh_r = (const float*)d_in[18];
    const float* fcw    = (const float*)d_in[19];
    const float* fcb    = (const float*)d_in[20];

    float* out  = (float*)d_out;               // [B, OUT] predictions
    float* outH = out + B_DIM * OUT_DIM;       // [L, B, H] hidden_out

    static float *p_ubwh = nullptr, *p_rnnin = nullptr, *p_gi = nullptr, *p_gh = nullptr;
    if (!p_ubwh) {
        cudaGetSymbolAddress((void**)&p_ubwh,  g_ubwh);
        cudaGetSymbolAddress((void**)&p_rnnin, g_rnnin);
        cudaGetSymbolAddress((void**)&p_gi,    g_gi);
        cudaGetSymbolAddress((void**)&p_gh,    g_gh);
    }

    const int BH = B_DIM * H_DIM;

    // 1) ubwh[b,o] = h_last @ Ww^T + Wb + Ub
    gemm_tn<<<dim3(H_DIM / 128, B_DIM / 64), 256>>>(
        hidden + 3 * BH, Ww, Wb, Ub, p_ubwh, B_DIM, H_DIM, H_DIM);

    // 2) fused attention-energy GEMM
    energy_kernel<<<(S_DIM * B_DIM) / 128, 256>>>(ES, Uw, aw);

    // 3) softmax over S
    softmax_kernel<<<2, 256>>>();

    // 4) context -> rnn_in[:, :H]; 5) embedding -> rnn_in[:, H:]
    context_kernel<<<B_DIM, dim3(128, 2)>>>(ES);
    embed_kernel<<<(B_DIM * E_DIM + 255) / 256, 256>>>(x, emb);

    // 6) 4-layer GRU (single timestep)
    for (int l = 0; l < L_DIM; ++l) {
        const float* A_in  = (l == 0) ? p_rnnin : (outH + (l - 1) * BH);
        int          K_in  = (l == 0) ? (H_DIM + E_DIM) : H_DIM;
        const float* wih   = (l == 0) ? w_ih0 : (w_ih_r + (size_t)(l - 1) * G3H * H_DIM);
        const float* whh   = (l == 0) ? w_hh0 : (w_hh_r + (size_t)(l - 1) * G3H * H_DIM);
        const float* bih   = (l == 0) ? b_ih0 : (b_ih_r + (size_t)(l - 1) * G3H);
        const float* bhh   = (l == 0) ? b_hh0 : (b_hh_r + (size_t)(l - 1) * G3H);

        gemm_tn<<<dim3(G3H / 128, B_DIM / 64), 256>>>(
            A_in, wih, bih, nullptr, p_gi, B_DIM, G3H, K_in);
        gemm_tn<<<dim3(G3H / 128, B_DIM / 64), 256>>>(
            hidden + (size_t)l * BH, whh, bhh, nullptr, p_gh, B_DIM, G3H, H_DIM);
        gru_gate<<<BH / 256, 256>>>(hidden + (size_t)l * BH, outH + (size_t)l * BH);
    }

    // 7) predictions = h3_new @ fcw^T + fcb
    gemm_tn<<<dim3(OUT_DIM / 128, B_DIM / 64), 256>>>(
        outH + 3 * BH, fcw, fcb, nullptr, out, B_DIM, OUT_DIM, H_DIM);
}

// round 2
// speedup vs baseline: 2.9698x; 2.9698x over previous
#include <cuda_runtime.h>
#include <math.h>
#include <stdint.h>

#define S_DIM 256
#define B_DIM 512
#define H_DIM 512
#define E_DIM 256
#define L_DIM 4
#define OUT_DIM 128
#define G3H (3 * H_DIM)
#define SB (S_DIM * B_DIM)

// ---------------- scratch (no allocations allowed) ----------------
__device__ float g_ubwh[B_DIM * H_DIM];       // Ub + Wb + h_last @ Ww^T
__device__ float g_epart[2 * SB];             // energy partials (2 n-tiles)
__device__ float g_att[SB];
__device__ float g_rnnin[B_DIM * (H_DIM + E_DIM)];
__device__ float g_gi[B_DIM * G3H];
__device__ float g_gh[B_DIM * G3H];

__device__ __forceinline__ float sigm(float x) { return 1.0f / (1.0f + expf(-x)); }

__device__ __forceinline__ uint32_t f2tf(float x) {
    uint32_t r;
    asm("cvt.rna.tf32.f32 %0, %1;" : "=r"(r) : "f"(x));
    return r;
}

__device__ __forceinline__ void mma_tf32(float c[4], const uint32_t a[4],
                                         uint32_t b0, uint32_t b1) {
    asm volatile(
        "mma.sync.aligned.m16n8k8.row.col.f32.tf32.tf32.f32 "
        "{%0,%1,%2,%3}, {%4,%5,%6,%7}, {%8,%9}, {%0,%1,%2,%3};\n"
        : "+f"(c[0]), "+f"(c[1]), "+f"(c[2]), "+f"(c[3])
        : "r"(a[0]), "r"(a[1]), "r"(a[2]), "r"(a[3]), "r"(b0), "r"(b1));
}

__device__ __forceinline__ void cp16(float* smem, const float* gmem) {
    uint32_t s = (uint32_t)__cvta_generic_to_shared(smem);
    asm volatile("cp.async.cg.shared.global [%0], [%1], 16;\n" :: "r"(s), "l"(gmem));
}
#define CP_COMMIT() asm volatile("cp.async.commit_group;\n")
#define CP_WAIT(n)  asm volatile("cp.async.wait_group %0;\n" :: "n"(n))

// =====================================================================
// Fused energy kernel (tf32 MMA):
//   epart[nt][s,b] = sum_{o in nt} tanh( ES[s,b,:].Uw[o,:] + ubwh[b,o] ) * aw[o]
// Block: 128 rows x 256 cols, K=512. 512 threads = 16 warps (4m x 4n),
// warp tile 32x64 (2 m-atoms, 8 n-atoms). cp.async double-buffered K=32 stages.
// =====================================================================
#define EN_SMEM ((2 * 128 * 36 + 2 * 256 * 36 + 128 * 4) * 4)

__global__ __launch_bounds__(512, 1) void energy_mma(
    const float* __restrict__ ES, const float* __restrict__ Uw,
    const float* __restrict__ aw)
{
    extern __shared__ float sm[];
    float* As  = sm;                     // [2][128][36]
    float* Ws  = sm + 2 * 128 * 36;      // [2][256][36]
    float* red = Ws + 2 * 256 * 36;      // [128][4]

    const int tid  = threadIdx.x;
    const int lane = tid & 31, warp = tid >> 5;
    const int g = lane >> 2, tig = lane & 3;
    const int mw = warp >> 2, nw = warp & 3;
    const int rowBase = blockIdx.x * 128;
    const int nT0 = blockIdx.y * 256;
    const int b0 = rowBase & (B_DIM - 1);

    const float* Abase = ES + (size_t)rowBase * 512;
    const float* Wbase = Uw + (size_t)nT0 * 512;

    auto prefetch = [&](int k0, int buf) {
#pragma unroll
        for (int q = 0; q < 2; q++) {
            int idx = q * 512 + tid;
            int r = idx >> 3, kq = (idx & 7) * 4;
            cp16(&As[(buf * 128 + r) * 36 + kq], Abase + (size_t)r * 512 + k0 + kq);
        }
#pragma unroll
        for (int q = 0; q < 4; q++) {
            int idx = q * 512 + tid;
            int r = idx >> 3, kq = (idx & 7) * 4;
            cp16(&Ws[(buf * 256 + r) * 36 + kq], Wbase + (size_t)r * 512 + k0 + kq);
        }
        CP_COMMIT();
    };

    float acc[2][8][4];
#pragma unroll
    for (int i = 0; i < 2; i++)
#pragma unroll
        for (int j = 0; j < 8; j++)
#pragma unroll
            for (int c = 0; c < 4; c++) acc[i][j][c] = 0.0f;

    prefetch(0, 0);

    for (int s = 0; s < 16; ++s) {
        int cur = s & 1;
        if (s < 15) { prefetch((s + 1) * 32, cur ^ 1); CP_WAIT(1); }
        else        { CP_WAIT(0); }
        __syncthreads();

        const float* Ab = &As[cur * 128 * 36];
        const float* Wb = &Ws[cur * 256 * 36];
#pragma unroll
        for (int ka = 0; ka < 4; ++ka) {
            int k = ka * 8;
            uint32_t Af[2][4];
#pragma unroll
            for (int ma = 0; ma < 2; ++ma) {
                int R = mw * 32 + ma * 16;
                Af[ma][0] = f2tf(Ab[(R + g) * 36 + k + tig]);
                Af[ma][1] = f2tf(Ab[(R + g + 8) * 36 + k + tig]);
                Af[ma][2] = f2tf(Ab[(R + g) * 36 + k + tig + 4]);
                Af[ma][3] = f2tf(Ab[(R + g + 8) * 36 + k + tig + 4]);
            }
#pragma unroll
            for (int na = 0; na < 8; ++na) {
                int C = nw * 64 + na * 8;
                uint32_t br0 = f2tf(Wb[(C + g) * 36 + k + tig]);
                uint32_t br1 = f2tf(Wb[(C + g) * 36 + k + tig + 4]);
#pragma unroll
                for (int ma = 0; ma < 2; ++ma)
                    mma_tf32(acc[ma][na], Af[ma], br0, br1);
            }
        }
        __syncthreads();
    }

    // epilogue: tanh(acc + ubwh)*aw, row-reduce
    float part[4];
#pragma unroll
    for (int ma = 0; ma < 2; ++ma) {
#pragma unroll
        for (int h = 0; h < 2; ++h) {
            int rl = mw * 32 + ma * 16 + h * 8 + g;
            int b  = b0 + rl;
            const float* ub = g_ubwh + (size_t)b * 512;
            float p = 0.0f;
#pragma unroll
            for (int na = 0; na < 8; ++na) {
                int col = nT0 + nw * 64 + na * 8 + tig * 2;
                float2 u = *(const float2*)(ub + col);
                float a0 = __ldg(aw + col), a1 = __ldg(aw + col + 1);
                p += tanhf(acc[ma][na][h * 2 + 0] + u.x) * a0;
                p += tanhf(acc[ma][na][h * 2 + 1] + u.y) * a1;
            }
            part[ma * 2 + h] = p;
        }
    }
#pragma unroll
    for (int i = 0; i < 4; i++) {
        part[i] += __shfl_xor_sync(0xffffffffu, part[i], 1);
        part[i] += __shfl_xor_sync(0xffffffffu, part[i], 2);
    }
    __syncthreads();
    if (tig == 0) {
#pragma unroll
        for (int ma = 0; ma < 2; ++ma)
#pragma unroll
            for (int h = 0; h < 2; ++h) {
                int rl = mw * 32 + ma * 16 + h * 8 + g;
                red[rl * 4 + nw] = part[ma * 2 + h];
            }
    }
    __syncthreads();
    if (tid < 128) {
        float e = red[tid * 4] + red[tid * 4 + 1] + red[tid * 4 + 2] + red[tid * 4 + 3];
        g_epart[blockIdx.y * SB + rowBase + tid] = e;
    }
}

// =====================================================================
// Generic tf32 GEMM: C = A[M,K] @ W[N,K]^T + bias (+bias2)
// BM=64, BN=128, 256 threads (2m x 4n warps, warp 32x32), K-stage 16, dbuf.
// blockIdx.z selects between two independent GEMM problems (GRU gi/gh).
// =====================================================================
__global__ __launch_bounds__(256) void gemm_tf32(
    const float* A0, const float* W0, const float* bias0, const float* bias2_0,
    float* C0, int K0,
    const float* A1, const float* W1, const float* bias1, float* C1, int K1,
    int M, int N)
{
    const float *A, *W, *bias, *bias2;
    float* C;
    int K;
    if (blockIdx.z == 0) { A = A0; W = W0; bias = bias0; bias2 = bias2_0; C = C0; K = K0; }
    else                 { A = A1; W = W1; bias = bias1; bias2 = nullptr; C = C1; K = K1; }

    __shared__ float sA[2 * 64 * 20];
    __shared__ float sW[2 * 128 * 20];

    const int tid  = threadIdx.x;
    const int lane = tid & 31, warp = tid >> 5;
    const int g = lane >> 2, tig = lane & 3;
    const int mw = warp >> 2, nw = warp & 3;   // 2 x 4
    const int m0 = blockIdx.y * 64;
    const int n0 = blockIdx.x * 128;

    const float* Abase = A + (size_t)m0 * K;
    const float* Wbase = W + (size_t)n0 * K;

    auto prefetch = [&](int k0, int buf) {
        {
            int r = tid >> 2, kq = (tid & 3) * 4;
            cp16(&sA[(buf * 64 + r) * 20 + kq], Abase + (size_t)r * K + k0 + kq);
        }
#pragma unroll
        for (int q = 0; q < 2; q++) {
            int idx = q * 256 + tid;
            int r = idx >> 2, kq = (idx & 3) * 4;
            cp16(&sW[(buf * 128 + r) * 20 + kq], Wbase + (size_t)r * K + k0 + kq);
        }
        CP_COMMIT();
    };

    float acc[2][4][4];
#pragma unroll
    for (int i = 0; i < 2; i++)
#pragma unroll
        for (int j = 0; j < 4; j++)
#pragma unroll
            for (int c = 0; c < 4; c++) acc[i][j][c] = 0.0f;

    prefetch(0, 0);
    const int nstage = K >> 4;
    for (int s = 0; s < nstage; ++s) {
        int cur = s & 1;
        if (s + 1 < nstage) { prefetch((s + 1) * 16, cur ^ 1); CP_WAIT(1); }
        else                { CP_WAIT(0); }
        __syncthreads();

        const float* Ab = &sA[cur * 64 * 20];
        const float* Wb = &sW[cur * 128 * 20];
#pragma unroll
        for (int ka = 0; ka < 2; ++ka) {
            int k = ka * 8;
            uint32_t Af[2][4];
#pragma unroll
            for (int ma = 0; ma < 2; ++ma) {
                int R = mw * 32 + ma * 16;
                Af[ma][0] = f2tf(Ab[(R + g) * 20 + k + tig]);
                Af[ma][1] = f2tf(Ab[(R + g + 8) * 20 + k + tig]);
                Af[ma][2] = f2tf(Ab[(R + g) * 20 + k + tig + 4]);
                Af[ma][3] = f2tf(Ab[(R + g + 8) * 20 + k + tig + 4]);
            }
#pragma unroll
            for (int na = 0; na < 4; ++na) {
                int Cc = nw * 32 + na * 8;
                uint32_t br0 = f2tf(Wb[(Cc + g) * 20 + k + tig]);
                uint32_t br1 = f2tf(Wb[(Cc + g) * 20 + k + tig + 4]);
#pragma unroll
                for (int ma = 0; ma < 2; ++ma)
                    mma_tf32(acc[ma][na], Af[ma], br0, br1);
            }
        }
        __syncthreads();
    }

    // epilogue: + bias (+bias2), store
#pragma unroll
    for (int ma = 0; ma < 2; ++ma) {
#pragma unroll
        for (int na = 0; na < 4; ++na) {
            int col = n0 + nw * 32 + na * 8 + tig * 2;
            float bb0 = bias[col]     + (bias2 ? bias2[col]     : 0.0f);
            float bb1 = bias[col + 1] + (bias2 ? bias2[col + 1] : 0.0f);
            int r0 = m0 + mw * 32 + ma * 16 + g;
            float2 v0 = make_float2(acc[ma][na][0] + bb0, acc[ma][na][1] + bb1);
            float2 v1 = make_float2(acc[ma][na][2] + bb0, acc[ma][na][3] + bb1);
            *(float2*)(C + (size_t)r0 * N + col)       = v0;
            *(float2*)(C + (size_t)(r0 + 8) * N + col) = v1;
        }
    }
}

// softmax over S per column b; combines the two n-tile energy partials.
__global__ void softmax_kernel()
{
    int b = blockIdx.x * blockDim.x + threadIdx.x;
    if (b >= B_DIM) return;
    float m = -1e30f;
#pragma unroll 8
    for (int s = 0; s < S_DIM; s++) {
        float e = __ldg(g_epart + s * B_DIM + b) + __ldg(g_epart + SB + s * B_DIM + b);
        m = fmaxf(m, e);
    }
    float sum = 0.0f;
#pragma unroll 8
    for (int s = 0; s < S_DIM; s++) {
        float e = expf(__ldg(g_epart + s * B_DIM + b) + __ldg(g_epart + SB + s * B_DIM + b) - m);
        g_att[s * B_DIM + b] = e;
        sum += e;
    }
    float inv = 1.0f / sum;
#pragma unroll 8
    for (int s = 0; s < S_DIM; s++) g_att[s * B_DIM + b] *= inv;
}

// context[b,h] = sum_s att[s,b] * ES[s,b,h] -> rnn_in[b, 0:H]
__global__ void context_kernel(const float* __restrict__ ES)
{
    const int b  = blockIdx.x;
    const int tx = threadIdx.x;   // 0..127 (h/4)
    const int sy = threadIdx.y;   // 0..1
    __shared__ float attS[256];
    __shared__ float4 buf[128];

    int tid = sy * 128 + tx;
    attS[tid] = g_att[tid * B_DIM + b];
    __syncthreads();

    float4 acc = make_float4(0.f, 0.f, 0.f, 0.f);
    const float4* base = (const float4*)ES;
    int s0 = sy * 128;
#pragma unroll 4
    for (int s = s0; s < s0 + 128; ++s) {
        float a = attS[s];
        float4 v = base[(size_t)(s * B_DIM + b) * 128 + tx];
        acc.x += a * v.x; acc.y += a * v.y; acc.z += a * v.z; acc.w += a * v.w;
    }
    if (sy == 1) buf[tx] = acc;
    __syncthreads();
    if (sy == 0) {
        float4 o = buf[tx];
        acc.x += o.x; acc.y += o.y; acc.z += o.z; acc.w += o.w;
        *(float4*)(g_rnnin + (size_t)b * (H_DIM + E_DIM) + tx * 4) = acc;
    }
}

// rnn_in[b, H : H+E] = emb[x[b]]
__global__ void embed_kernel(const int* __restrict__ x, const float* __restrict__ emb)
{
    int idx = blockIdx.x * blockDim.x + threadIdx.x;
    if (idx >= B_DIM * E_DIM) return;
    int b = idx >> 8, e = idx & 255;
    g_rnnin[(size_t)b * (H_DIM + E_DIM) + H_DIM + e] = emb[(size_t)x[b] * E_DIM + e];
}

// GRU gate math
__global__ void gru_gate(const float* __restrict__ hprev, float* __restrict__ hout)
{
    int idx = blockIdx.x * blockDim.x + threadIdx.x;
    if (idx >= B_DIM * H_DIM) return;
    int b = idx >> 9, j = idx & 511;
    const float* gib = g_gi + (size_t)b * G3H;
    const float* ghb = g_gh + (size_t)b * G3H;
    float r = sigm(gib[j] + ghb[j]);
    float z = sigm(gib[H_DIM + j] + ghb[H_DIM + j]);
    float n = tanhf(gib[2 * H_DIM + j] + r * ghb[2 * H_DIM + j]);
    hout[idx] = (1.0f - z) * n + z * hprev[idx];
}

// =====================================================================
extern "C" void kernel_launch(void* const* d_in, const int* in_sizes, int n_in,
                              void* d_out, int out_size)
{
    const int*   x      = (const int*)  d_in[0];
    const float* ES     = (const float*)d_in[1];
    const float* hidden = (const float*)d_in[2];
    const float* emb    = (const float*)d_in[4];
    const float* Uw     = (const float*)d_in[5];
    const float* Ub     = (const float*)d_in[6];
    const float* Ww     = (const float*)d_in[7];
    const float* Wb     = (const float*)d_in[8];
    const float* aw     = (const float*)d_in[9];
    const float* w_ih0  = (const float*)d_in[11];
    const float* w_hh0  = (const float*)d_in[12];
    const float* b_ih0  = (const float*)d_in[13];
    const float* b_hh0  = (const float*)d_in[14];
    const float* w_ih_r = (const float*)d_in[15];
    const float* w_hh_r = (const float*)d_in[16];
    const float* b_ih_r = (const float*)d_in[17];
    const float* b_hh_r = (const float*)d_in[18];
    const float* fcw    = (const float*)d_in[19];
    const float* fcb    = (const float*)d_in[20];

    float* out  = (float*)d_out;               // [B, OUT]
    float* outH = out + B_DIM * OUT_DIM;       // [L, B, H]

    static float *p_ubwh = nullptr, *p_rnnin = nullptr, *p_gi = nullptr, *p_gh = nullptr;
    if (!p_ubwh) {
        cudaGetSymbolAddress((void**)&p_ubwh,  g_ubwh);
        cudaGetSymbolAddress((void**)&p_rnnin, g_rnnin);
        cudaGetSymbolAddress((void**)&p_gi,    g_gi);
        cudaGetSymbolAddress((void**)&p_gh,    g_gh);
        cudaFuncSetAttribute(energy_mma, cudaFuncAttributeMaxDynamicSharedMemorySize, EN_SMEM);
    }

    const int BH = B_DIM * H_DIM;

    // 1) ubwh[b,o] = h_last @ Ww^T + Wb + Ub
    gemm_tf32<<<dim3(H_DIM / 128, B_DIM / 64, 1), 256>>>(
        hidden + 3 * BH, Ww, Wb, Ub, p_ubwh, H_DIM,
        hidden + 3 * BH, Ww, Wb, p_ubwh, H_DIM, B_DIM, H_DIM);

    // 2) fused attention-energy (tf32 MMA), 2 n-tiles -> partials
    energy_mma<<<dim3(SB / 128, 2, 1), 512, EN_SMEM>>>(ES, Uw, aw);

    // 3) softmax over S
    softmax_kernel<<<2, 256>>>();

    // 4) context + embedding
    context_kernel<<<B_DIM, dim3(128, 2)>>>(ES);
    embed_kernel<<<(B_DIM * E_DIM + 255) / 256, 256>>>(x, emb);

    // 5) 4-layer GRU: gi and gh batched via blockIdx.z
    for (int l = 0; l < L_DIM; ++l) {
        const float* A_in = (l == 0) ? p_rnnin : (outH + (size_t)(l - 1) * BH);
        int          K_in = (l == 0) ? (H_DIM + E_DIM) : H_DIM;
        const float* wih  = (l == 0) ? w_ih0 : (w_ih_r + (size_t)(l - 1) * G3H * H_DIM);
        const float* whh  = (l == 0) ? w_hh0 : (w_hh_r + (size_t)(l - 1) * G3H * H_DIM);
        const float* bih  = (l == 0) ? b_ih0 : (b_ih_r + (size_t)(l - 1) * G3H);
        const float* bhh  = (l == 0) ? b_hh0 : (b_hh_r + (size_t)(l - 1) * G3H);

        gemm_tf32<<<dim3(G3H / 128, B_DIM / 64, 2), 256>>>(
            A_in, wih, bih, nullptr, p_gi, K_in,
            hidden + (size_t)l * BH, whh, bhh, p_gh, H_DIM, B_DIM, G3H);
        gru_gate<<<BH / 256, 256>>>(hidden + (size_t)l * BH, outH + (size_t)l * BH);
    }

    // 6) predictions = h3_new @ fcw^T + fcb
    gemm_tf32<<<dim3(OUT_DIM / 128, B_DIM / 64, 1), 256>>>(
        outH + 3 * BH, fcw, fcb, nullptr, out, H_DIM,
        outH + 3 * BH, fcw, fcb, out, H_DIM, B_DIM, OUT_DIM);
}